// round 5
// baseline (speedup 1.0000x reference)
#include <cuda_runtime.h>
#include <cstdint>
#include <math.h>

#define BB 128
#define NN 1000
#define DD 196
#define KK 48
#define NC 64            // candidate columns (top-NC of x per batch row)
#define NO (DD - NC)     // 132 other columns
#define NWARPS 24
#define THREADS (NWARPS * 32)

__device__ __forceinline__ unsigned f2key(float v) {
    unsigned u = __float_as_uint(v);
    return u ^ ((unsigned)((int)u >> 31) | 0x80000000u);
}

// Exact full-width fallback: top-KK of all 196 perturbed values, d-ascending ranks.
__device__ __noinline__ void fallback_select(const float* __restrict__ row,
                                             const float* __restrict__ xb,
                                             float sigma, int* acc,
                                             int lane, unsigned lt)
{
    const unsigned FULL = 0xffffffffu;
    unsigned key[7];
#pragma unroll
    for (int j = 0; j < 7; ++j) {
        int d = j * 32 + lane;
        key[j] = (d < DD) ? f2key(fmaf(sigma, row[d], xb[d])) : 0u;
    }
    unsigned prefix = 0;
    for (int bit = 31; bit >= 0; --bit) {
        unsigned t = prefix | (1u << bit);
        int c = 0;
#pragma unroll
        for (int j = 0; j < 7; ++j) c += (key[j] >= t);
        c = __reduce_add_sync(FULL, c);
        if (c >= KK) { prefix = t; if (c == KK) break; }
    }
    int cgt = 0;
#pragma unroll
    for (int j = 0; j < 7; ++j) cgt += (key[j] > prefix);
    cgt = __reduce_add_sync(FULL, cgt);
    int rem = KK - cgt;
    int selb = 0, eqb = 0;
#pragma unroll
    for (int j = 0; j < 7; ++j) {
        bool gt = key[j] > prefix;
        bool eq = (key[j] == prefix);
        unsigned be = __ballot_sync(FULL, eq);
        bool sel = gt || (eq && (eqb + __popc(be & lt)) < rem);
        unsigned bs = __ballot_sync(FULL, sel);
        if (sel) atomicAdd(&acc[(selb + __popc(bs & lt)) * DD + (j * 32 + lane)], 1);
        eqb += __popc(be);
        selb += __popc(bs);
    }
}

// Process S samples (n0 + s*NWARPS) with interleaved (lockstep) radix selects.
template<int S>
__device__ __forceinline__ void process(
    const float* __restrict__ nbase, int n0,
    const float* __restrict__ xb, float sigma,
    int dC0, int dC1, float xC0, float xC1,
    const int* __restrict__ dO, const float* __restrict__ xO,
    int* acc, int lane, unsigned lt)
{
    const unsigned FULL = 0xffffffffu;
    unsigned k0[S], k1[S], moK[S];
#pragma unroll
    for (int s = 0; s < S; ++s) {
        const float* row = nbase + (size_t)(n0 + s * NWARPS) * DD;
        float mo = -INFINITY;
#pragma unroll
        for (int j = 0; j < 5; ++j) mo = fmaxf(mo, fmaf(sigma, row[dO[j]], xO[j]));
        k0[s] = f2key(fmaf(sigma, row[dC0], xC0));
        k1[s] = f2key(fmaf(sigma, row[dC1], xC1));
        moK[s] = f2key(mo);
    }
    unsigned A[S], O[S];
#pragma unroll
    for (int s = 0; s < S; ++s) A[s] = __reduce_and_sync(FULL, k0[s] & k1[s]);
#pragma unroll
    for (int s = 0; s < S; ++s) O[s] = __reduce_or_sync(FULL, k0[s] | k1[s]);
#pragma unroll
    for (int s = 0; s < S; ++s) moK[s] = __reduce_max_sync(FULL, moK[s]);

    unsigned pr[S]; int bit[S]; bool done[S];
#pragma unroll
    for (int s = 0; s < S; ++s) {
        unsigned xr = A[s] ^ O[s];
        if (xr == 0u) { pr[s] = A[s]; bit[s] = -1; done[s] = true; }
        else {
            int hb = 31 - __clz(xr);
            int sb = hb | 1;                 // odd start -> clean 2-bit rounds to bit 0
            pr[s] = (sb >= 31) ? 0u : ((A[s] >> (sb + 1)) << (sb + 1));
            bit[s] = sb; done[s] = false;
        }
    }

    // Lockstep 2-bit radix rounds: one packed REDUX per sample per round,
    // the S REDUX chains overlap in latency.
    for (;;) {
        bool any = false;
#pragma unroll
        for (int s = 0; s < S; ++s) any |= !done[s];
        if (!any) break;

        unsigned pc[S], t1[S], t2[S], t3[S];
#pragma unroll
        for (int s = 0; s < S; ++s) {
            int bb = done[s] ? 1 : bit[s];
            t1[s] = pr[s] | (1u << (bb - 1));
            t2[s] = pr[s] | (2u << (bb - 1));
            t3[s] = pr[s] | (3u << (bb - 1));
            pc[s] = (unsigned)((k0[s] >= t1[s]) + (k1[s] >= t1[s]))
                  | ((unsigned)((k0[s] >= t2[s]) + (k1[s] >= t2[s])) << 10)
                  | ((unsigned)((k0[s] >= t3[s]) + (k1[s] >= t3[s])) << 20);
        }
#pragma unroll
        for (int s = 0; s < S; ++s) pc[s] = __reduce_add_sync(FULL, pc[s]);
#pragma unroll
        for (int s = 0; s < S; ++s) {
            if (done[s]) continue;
            int c1 = pc[s] & 1023, c2 = (pc[s] >> 10) & 1023, c3 = (int)(pc[s] >> 20);
            if      (c3 >= KK) { pr[s] = t3[s]; if (c3 == KK) done[s] = true; }
            else if (c2 >= KK) { pr[s] = t2[s]; if (c2 == KK) done[s] = true; }
            else if (c1 >= KK) { pr[s] = t1[s]; if (c1 == KK) done[s] = true; }
            bit[s] -= 2;
            if (bit[s] < 1) done[s] = true;
        }
    }

    // Verify + scatter per sample.
#pragma unroll
    for (int s = 0; s < S; ++s) {
        unsigned vT = pr[s];
        if (moK[s] >= vT) {
            // a non-candidate might enter top-48 (or tie): exact full path
            const float* row = nbase + (size_t)(n0 + s * NWARPS) * DD;
            fallback_select(row, xb, sigma, acc, lane, lt);
            continue;
        }
        int cgt = __reduce_add_sync(FULL, (int)(k0[s] > vT) + (int)(k1[s] > vT));
        int rem = KK - cgt;

        bool gt = k0[s] > vT, eq = (k0[s] == vT);
        unsigned be = __ballot_sync(FULL, eq);
        bool sel = gt || (eq && (__popc(be & lt)) < rem);
        unsigned bs = __ballot_sync(FULL, sel);
        if (sel) atomicAdd(&acc[(__popc(bs & lt)) * DD + dC0], 1);
        int eqb = __popc(be), selb = __popc(bs);

        gt = k1[s] > vT; eq = (k1[s] == vT);
        be = __ballot_sync(FULL, eq);
        sel = gt || (eq && (eqb + __popc(be & lt)) < rem);
        bs = __ballot_sync(FULL, sel);
        if (sel) atomicAdd(&acc[(selb + __popc(bs & lt)) * DD + dC1], 1);
    }
}

__global__ __launch_bounds__(THREADS, 1)
void ptk_kernel(const float* __restrict__ x,
                const float* __restrict__ noise,
                const float* __restrict__ sigma_p,
                float* __restrict__ out)
{
    __shared__ int acc[KK * DD];   // 37632 B
    __shared__ short cidx[NC];     // candidate column ids, ascending d
    __shared__ short oidx[NO];     // other column ids, ascending d

    const int b = blockIdx.x, tid = threadIdx.x, lane = tid & 31, warp = tid >> 5;
    const unsigned lt = (1u << lane) - 1u;
    const unsigned FULL = 0xffffffffu;

    for (int i = tid; i < KK * DD; i += THREADS) acc[i] = 0;

    // ---- per-b precompute (warp 0): exact top-NC columns of x ----
    if (warp == 0) {
        unsigned key[7];
#pragma unroll
        for (int j = 0; j < 7; ++j) {
            int d = j * 32 + lane;
            key[j] = (d < DD) ? f2key(x[b * DD + d]) : 0u;
        }
        unsigned prefix = 0;
        for (int bit = 31; bit >= 0; --bit) {
            unsigned t = prefix | (1u << bit);
            int c = 0;
#pragma unroll
            for (int j = 0; j < 7; ++j) c += (key[j] >= t);
            c = __reduce_add_sync(FULL, c);
            if (c >= NC) { prefix = t; if (c == NC) break; }
        }
        int cgt = 0;
#pragma unroll
        for (int j = 0; j < 7; ++j) cgt += (key[j] > prefix);
        cgt = __reduce_add_sync(FULL, cgt);
        int rem = NC - cgt;
        int cb = 0, ob = 0, eqb = 0;
#pragma unroll
        for (int j = 0; j < 7; ++j) {
            int d = j * 32 + lane;
            bool valid = d < DD;
            bool gt = key[j] > prefix;
            bool eq = valid && (key[j] == prefix);
            unsigned be = __ballot_sync(FULL, eq);
            bool sel = gt || (eq && (eqb + __popc(be & lt)) < rem);
            unsigned bs = __ballot_sync(FULL, sel);
            unsigned bo = __ballot_sync(FULL, valid && !sel);
            if (sel)        cidx[cb + __popc(bs & lt)] = (short)d;
            else if (valid) oidx[ob + __popc(bo & lt)] = (short)d;
            eqb += __popc(be); cb += __popc(bs); ob += __popc(bo);
        }
    }
    __syncthreads();

    const float sigma = sigma_p ? *sigma_p : 0.05f;
    const float* xb = x + b * DD;

    // per-lane static gather indices + x values
    const int dC0 = cidx[lane];
    const int dC1 = cidx[32 + lane];
    const float xC0 = xb[dC0];
    const float xC1 = xb[dC1];
    int dO[5]; float xO[5];
#pragma unroll
    for (int j = 0; j < 5; ++j) {
        int p = j * 32 + lane;
        if (p < NO) { dO[j] = oidx[p]; xO[j] = xb[dO[j]]; }
        else        { dO[j] = 0;       xO[j] = -INFINITY; }
    }

    const float* nbase = noise + (size_t)b * NN * DD;

    int n = warp;
    for (; n + NWARPS < NN; n += 2 * NWARPS)
        process<2>(nbase, n, xb, sigma, dC0, dC1, xC0, xC1, dO, xO, acc, lane, lt);
    if (n < NN)
        process<1>(nbase, n, xb, sigma, dC0, dC1, xC0, xC1, dO, xO, acc, lane, lt);

    __syncthreads();

    const float inv = 1.0f / (float)NN;
    float* ob = out + (size_t)b * KK * DD;
    for (int i = tid; i < KK * DD; i += THREADS)
        ob[i] = (float)acc[i] * inv;
}

extern "C" void kernel_launch(void* const* d_in, const int* in_sizes, int n_in,
                              void* d_out, int out_size)
{
    const float* x     = nullptr;
    const float* noise = nullptr;
    const float* sigma = nullptr;
    for (int i = 0; i < n_in; ++i) {
        if      (in_sizes[i] == BB * DD)      x     = (const float*)d_in[i];
        else if (in_sizes[i] == BB * NN * DD) noise = (const float*)d_in[i];
        else if (in_sizes[i] == 1)            sigma = (const float*)d_in[i];
    }
    ptk_kernel<<<BB, THREADS>>>(x, noise, sigma, (float*)d_out);
}

// round 6
// speedup vs baseline: 1.2390x; 1.2390x over previous
#include <cuda_runtime.h>
#include <cstdint>
#include <math.h>

#define BB 128
#define NN 1000
#define DD 196
#define KK 48
#define NC 64            // candidate columns (top-NC of x per batch row)
#define NO (DD - NC)     // 132 other columns
#define NWARPS 16
#define THREADS (NWARPS * 32)
#define RECW 68          // words per record: 64 keys + moK + pad (16B-aligned stride)

// dynamic smem layout (bytes)
#define OFF_ACC   0
#define SZ_ACC    (KK * DD * 4)                 // 37632
#define OFF_RECS  (OFF_ACC + SZ_ACC)            // 37632 (16B aligned)
#define SZ_RECS   (NWARPS * 32 * RECW * 4)      // 139264
#define OFF_CIDX  (OFF_RECS + SZ_RECS)          // 176896
#define OFF_OIDX  (OFF_CIDX + NC * 2)           // 177024
#define OFF_FLAGC (OFF_OIDX + NO * 2)           // 177288
#define OFF_FLAGN (OFF_FLAGC + 4)               // 177292
#define SMEM_TOTAL (OFF_FLAGN + NN * 2 + 16)    // ~179.3 KB

__device__ __forceinline__ unsigned f2key(float v) {
    unsigned u = __float_as_uint(v);
    return u ^ ((unsigned)((int)u >> 31) | 0x80000000u);
}

// Exact full-width fallback: top-KK of all 196 perturbed values, d-ascending ranks.
__device__ __noinline__ void fallback_select(const float* __restrict__ row,
                                             const float* __restrict__ xb,
                                             float sigma, int* acc,
                                             int lane, unsigned lt)
{
    const unsigned FULL = 0xffffffffu;
    unsigned key[7];
#pragma unroll
    for (int j = 0; j < 7; ++j) {
        int d = j * 32 + lane;
        key[j] = (d < DD) ? f2key(fmaf(sigma, row[d], xb[d])) : 0u;
    }
    unsigned prefix = 0;
    for (int bit = 31; bit >= 0; --bit) {
        unsigned t = prefix | (1u << bit);
        int c = 0;
#pragma unroll
        for (int j = 0; j < 7; ++j) c += (key[j] >= t);
        c = __reduce_add_sync(FULL, c);
        if (c >= KK) { prefix = t; if (c == KK) break; }
    }
    int cgt = 0;
#pragma unroll
    for (int j = 0; j < 7; ++j) cgt += (key[j] > prefix);
    cgt = __reduce_add_sync(FULL, cgt);
    int rem = KK - cgt;
    int selb = 0, eqb = 0;
#pragma unroll
    for (int j = 0; j < 7; ++j) {
        bool gt = key[j] > prefix;
        bool eq = (key[j] == prefix);
        unsigned be = __ballot_sync(FULL, eq);
        bool sel = gt || (eq && (eqb + __popc(be & lt)) < rem);
        unsigned bs = __ballot_sync(FULL, sel);
        if (sel) atomicAdd(&acc[(selb + __popc(bs & lt)) * DD + (j * 32 + lane)], 1);
        eqb += __popc(be);
        selb += __popc(bs);
    }
}

__global__ __launch_bounds__(THREADS, 1)
void ptk_kernel(const float* __restrict__ x,
                const float* __restrict__ noise,
                const float* __restrict__ sigma_p,
                float* __restrict__ out)
{
    extern __shared__ char smem_raw[];
    int*      acc     = (int*)(smem_raw + OFF_ACC);
    unsigned* recs    = (unsigned*)(smem_raw + OFF_RECS);
    short*    cidx    = (short*)(smem_raw + OFF_CIDX);
    short*    oidx    = (short*)(smem_raw + OFF_OIDX);
    int*      flagCnt = (int*)(smem_raw + OFF_FLAGC);
    short*    flagN   = (short*)(smem_raw + OFF_FLAGN);

    const int b = blockIdx.x, tid = threadIdx.x, lane = tid & 31, warp = tid >> 5;
    const unsigned lt = (1u << lane) - 1u;
    const unsigned FULL = 0xffffffffu;

    for (int i = tid; i < KK * DD; i += THREADS) acc[i] = 0;
    if (tid == 0) *flagCnt = 0;

    // ---- per-b precompute (warp 0): exact top-NC columns of x ----
    if (warp == 0) {
        unsigned key[7];
#pragma unroll
        for (int j = 0; j < 7; ++j) {
            int d = j * 32 + lane;
            key[j] = (d < DD) ? f2key(x[b * DD + d]) : 0u;
        }
        unsigned prefix = 0;
        for (int bit = 31; bit >= 0; --bit) {
            unsigned t = prefix | (1u << bit);
            int c = 0;
#pragma unroll
            for (int j = 0; j < 7; ++j) c += (key[j] >= t);
            c = __reduce_add_sync(FULL, c);
            if (c >= NC) { prefix = t; if (c == NC) break; }
        }
        int cgt = 0;
#pragma unroll
        for (int j = 0; j < 7; ++j) cgt += (key[j] > prefix);
        cgt = __reduce_add_sync(FULL, cgt);
        int rem = NC - cgt;
        int cb = 0, ob = 0, eqb = 0;
#pragma unroll
        for (int j = 0; j < 7; ++j) {
            int d = j * 32 + lane;
            bool valid = d < DD;
            bool gt = key[j] > prefix;
            bool eq = valid && (key[j] == prefix);
            unsigned be = __ballot_sync(FULL, eq);
            bool sel = gt || (eq && (eqb + __popc(be & lt)) < rem);
            unsigned bs = __ballot_sync(FULL, sel);
            unsigned bo = __ballot_sync(FULL, valid && !sel);
            if (sel)        cidx[cb + __popc(bs & lt)] = (short)d;
            else if (valid) oidx[ob + __popc(bo & lt)] = (short)d;
            eqb += __popc(be); cb += __popc(bs); ob += __popc(bo);
        }
    }
    __syncthreads();

    const float sigma = sigma_p ? *sigma_p : 0.05f;
    const float* xb = x + b * DD;

    // per-lane static gather indices + x values (gather frontend, as R4)
    const int dC0 = cidx[lane];
    const int dC1 = cidx[32 + lane];
    const float xC0 = xb[dC0];
    const float xC1 = xb[dC1];
    int dO[5]; float xO[5];
#pragma unroll
    for (int j = 0; j < 5; ++j) {
        int p = j * 32 + lane;
        if (p < NO) { dO[j] = oidx[p]; xO[j] = xb[dO[j]]; }
        else        { dO[j] = 0;       xO[j] = -INFINITY; }
    }

    const float* nbase = noise + (size_t)b * NN * DD;
    unsigned* myrecs = recs + warp * 32 * RECW;

    const int wstart = (NN * warp) / NWARPS;
    const int wend   = (NN * (warp + 1)) / NWARPS;

    for (int base = wstart; base < wend; base += 32) {
        const int m = min(32, wend - base);

        // ---- phase 1 (warp-coop): gather keys for m rows, groups of 4 for MLP ----
        for (int g = 0; g < m; g += 4) {
            const int gm = min(4, m - g);
            float c0[4], c1[4], o0[4], o1[4], o2[4], o3[4], o4[4];
#pragma unroll
            for (int t = 0; t < 4; ++t) {
                const float* row = nbase + (size_t)(base + g + ((t < gm) ? t : 0)) * DD;
                c0[t] = row[dC0]; c1[t] = row[dC1];
                o0[t] = row[dO[0]]; o1[t] = row[dO[1]]; o2[t] = row[dO[2]];
                o3[t] = row[dO[3]]; o4[t] = row[dO[4]];
            }
#pragma unroll
            for (int t = 0; t < 4; ++t) {
                if (t >= gm) break;
                float mo = fmaf(sigma, o0[t], xO[0]);
                mo = fmaxf(mo, fmaf(sigma, o1[t], xO[1]));
                mo = fmaxf(mo, fmaf(sigma, o2[t], xO[2]));
                mo = fmaxf(mo, fmaf(sigma, o3[t], xO[3]));
                mo = fmaxf(mo, fmaf(sigma, o4[t], xO[4]));
                unsigned k0 = f2key(fmaf(sigma, c0[t], xC0));
                unsigned k1 = f2key(fmaf(sigma, c1[t], xC1));
                unsigned moK = __reduce_max_sync(FULL, f2key(mo));
                unsigned* rec = myrecs + (g + t) * RECW;
                rec[lane] = k0;
                rec[32 + lane] = k1;
                if (lane == 0) rec[64] = moK;
            }
        }
        __syncwarp();

        // ---- phase 2 (per-thread): exact top-48 of this lane's record ----
        if (lane < m) {
            unsigned k[64];
            const uint4* rp = (const uint4*)(myrecs + lane * RECW);
#pragma unroll
            for (int i = 0; i < 16; ++i) {
                uint4 v = rp[i];
                k[4 * i] = v.x; k[4 * i + 1] = v.y; k[4 * i + 2] = v.z; k[4 * i + 3] = v.w;
            }
            unsigned moK = myrecs[lane * RECW + 64];

            // min/max (4 parallel chains)
            unsigned lo0 = k[0], lo1 = k[1], lo2 = k[2], lo3 = k[3];
            unsigned hi0 = k[0], hi1 = k[1], hi2 = k[2], hi3 = k[3];
#pragma unroll
            for (int j = 4; j < 64; j += 4) {
                lo0 = min(lo0, k[j]);     hi0 = max(hi0, k[j]);
                lo1 = min(lo1, k[j + 1]); hi1 = max(hi1, k[j + 1]);
                lo2 = min(lo2, k[j + 2]); hi2 = max(hi2, k[j + 2]);
                lo3 = min(lo3, k[j + 3]); hi3 = max(hi3, k[j + 3]);
            }
            unsigned kmin = min(min(lo0, lo1), min(lo2, lo3));
            unsigned kmax = max(max(hi0, hi1), max(hi2, hi3));

            unsigned vT;
            if (kmin == kmax) {
                vT = kmin;
            } else {
                int hb = 31 - __clz(kmin ^ kmax);
                unsigned prefix = (hb >= 31) ? 0u : (kmin & ~((1u << (hb + 1)) - 1u));
                for (int bit = hb; bit >= 0; --bit) {
                    unsigned t = prefix | (1u << bit);
                    int ca = 0, cb2 = 0, cc = 0, cd = 0;
#pragma unroll
                    for (int j = 0; j < 64; j += 4) {
                        ca += (k[j] >= t); cb2 += (k[j + 1] >= t);
                        cc += (k[j + 2] >= t); cd += (k[j + 3] >= t);
                    }
                    int c = (ca + cb2) + (cc + cd);
                    if (c >= KK) { prefix = t; if (c == KK) break; }
                }
                vT = prefix;
            }

            if (moK >= vT) {
                int idx = atomicAdd(flagCnt, 1);
                if (idx < NN) flagN[idx] = (short)(base + lane);
            } else {
                int cgt = 0;
#pragma unroll
                for (int j = 0; j < 64; ++j) cgt += (k[j] > vT);
                int rem = KK - cgt;
                int eqs = 0, selr = 0;
#pragma unroll
                for (int j = 0; j < 64; ++j) {
                    bool gt = k[j] > vT;
                    bool eq = (k[j] == vT);
                    bool sel = gt || (eq && (eqs < rem));
                    eqs += eq;
                    if (sel) atomicAdd(&acc[selr * DD + (int)cidx[j]], 1);
                    selr += sel;
                }
            }
        }
        __syncwarp();
    }

    __syncthreads();

    // ---- exact fallback for flagged rows (warp-cooperative, rare) ----
    {
        const int fc = min(*flagCnt, NN);
        for (int f = warp; f < fc; f += NWARPS) {
            const float* row = nbase + (size_t)flagN[f] * DD;
            fallback_select(row, xb, sigma, acc, lane, lt);
        }
    }
    __syncthreads();

    const float inv = 1.0f / (float)NN;
    float* ob = out + (size_t)b * KK * DD;
    for (int i = tid; i < KK * DD; i += THREADS)
        ob[i] = (float)acc[i] * inv;
}

extern "C" void kernel_launch(void* const* d_in, const int* in_sizes, int n_in,
                              void* d_out, int out_size)
{
    const float* x     = nullptr;
    const float* noise = nullptr;
    const float* sigma = nullptr;
    for (int i = 0; i < n_in; ++i) {
        if      (in_sizes[i] == BB * DD)      x     = (const float*)d_in[i];
        else if (in_sizes[i] == BB * NN * DD) noise = (const float*)d_in[i];
        else if (in_sizes[i] == 1)            sigma = (const float*)d_in[i];
    }
    cudaFuncSetAttribute(ptk_kernel, cudaFuncAttributeMaxDynamicSharedMemorySize,
                         SMEM_TOTAL);
    ptk_kernel<<<BB, THREADS, SMEM_TOTAL>>>(x, noise, sigma, (float*)d_out);
}